// round 8
// baseline (speedup 1.0000x reference)
#include <cuda_runtime.h>
#include <cuda_fp16.h>
#include <math.h>
#include <stdint.h>

// HashEmbedder: 16-level 2D multires hash grid, 2 feats/level, T=2^19.
// Pipeline per launch:
//   0. zero bucket counters
//   1. histogram points into 256x256 spatial buckets
//   2. one-block exclusive scan -> bucket bases/cursors
//   3. scatter points into bucket order (xy + orig index)
//   4. build fp16 cell-packed corner table (16B/cell)
//   5. main: 4 thr/point over SORTED points -> warp-local spatial locality
//      collapses gather lines (coarse levels ~1 line per 8 points).

#define NLEV 16
#define TLOG2 19
#define TSIZE (1u << TLOG2)
#define HMASK ((1u << TLOG2) - 1u)
#define PRIME1 2654435761u

#define NPOINTS_MAX 1000448
#define GRIDB 256                 // buckets per axis
#define NBUCK (GRIDB * GRIDB)     // 65536

// Sum of res^2 over the 16 levels = 706,816 cells; margin for safety.
#define MAX_CELLS 710000
__device__ uint4  g_packed[MAX_CELLS];
__device__ int    g_count[NBUCK];
__device__ int    g_cursor[NBUCK];
__device__ float2 g_xy_sorted[NPOINTS_MAX];
__device__ int    g_orig[NPOINTS_MAX];

struct Params {
    float resF[NLEV];
    int   resI[NLEV];
    int   off[NLEV + 1];
};

__device__ __forceinline__ int bucket_of(float2 xy) {
    int bx = min(max((int)(xy.x * (float)GRIDB), 0), GRIDB - 1);
    int by = min(max((int)(xy.y * (float)GRIDB), 0), GRIDB - 1);
    return by * GRIDB + bx;
}

// ---------------------------------------------------------------------------
__global__ void zero_counts_kernel() {
    int i = blockIdx.x * blockDim.x + threadIdx.x;
    if (i < NBUCK) g_count[i] = 0;
}

__global__ void hist_kernel(const float* __restrict__ x, int n_points) {
    int p = blockIdx.x * blockDim.x + threadIdx.x;
    if (p >= n_points) return;
    float2 xy = __ldg(((const float2*)x) + p);
    atomicAdd(&g_count[bucket_of(xy)], 1);
}

// One block, 1024 threads, 64 buckets per thread.
__global__ __launch_bounds__(1024) void scan_kernel() {
    __shared__ int sh[1024];
    int t = threadIdx.x;

    int s = 0;
#pragma unroll 4
    for (int k = 0; k < 64; ++k) s += g_count[t * 64 + k];

    sh[t] = s;
    __syncthreads();
    // Hillis-Steele inclusive scan
    for (int d = 1; d < 1024; d <<= 1) {
        int v = (t >= d) ? sh[t - d] : 0;
        __syncthreads();
        sh[t] += v;
        __syncthreads();
    }
    int running = sh[t] - s;   // exclusive offset for this thread's chunk

    for (int k = 0; k < 64; ++k) {
        int i = t * 64 + k;
        g_cursor[i] = running;
        running += g_count[i];
    }
}

__global__ void scatter_kernel(const float* __restrict__ x, int n_points) {
    int p = blockIdx.x * blockDim.x + threadIdx.x;
    if (p >= n_points) return;
    float2 xy = __ldg(((const float2*)x) + p);
    int pos = atomicAdd(&g_cursor[bucket_of(xy)], 1);
    g_xy_sorted[pos] = xy;
    g_orig[pos] = p;
}

// ---------------------------------------------------------------------------
// Build packed table. One thread per cell.
// ---------------------------------------------------------------------------
__global__ __launch_bounds__(256) void build_packed_kernel(
    const float* __restrict__ emb, Params pm, int total_cells)
{
    int i = blockIdx.x * blockDim.x + threadIdx.x;
    if (i >= total_cells) return;

    int l = 0;
#pragma unroll
    for (int k = 1; k < NLEV; ++k) l += (i >= pm.off[k]);

    int c   = i - pm.off[l];
    int res = pm.resI[l];
    int cy  = c / res;
    int cx  = c - cy * res;

    uint32_t ux0 = (uint32_t)cx;
    uint32_t ux1 = (uint32_t)(cx + 1);
    uint32_t yp0 = (uint32_t)cy * PRIME1;
    uint32_t yp1 = (uint32_t)(cy + 1) * PRIME1;

    uint32_t a00 = (ux0 ^ yp0) & HMASK;
    uint32_t a10 = (ux1 ^ yp0) & HMASK;
    uint32_t a01 = (ux0 ^ yp1) & HMASK;
    uint32_t a11 = (ux1 ^ yp1) & HMASK;

    const float2* __restrict__ tab =
        ((const float2*)emb) + ((size_t)l << TLOG2);

    float2 f00 = __ldg(tab + a00);
    float2 f10 = __ldg(tab + a10);
    float2 f01 = __ldg(tab + a01);
    float2 f11 = __ldg(tab + a11);

    half2 h00 = __float22half2_rn(f00);
    half2 h10 = __float22half2_rn(f10);
    half2 h01 = __float22half2_rn(f01);
    half2 h11 = __float22half2_rn(f11);

    uint4 r;
    r.x = *(const uint32_t*)&h00;
    r.y = *(const uint32_t*)&h10;
    r.z = *(const uint32_t*)&h01;
    r.w = *(const uint32_t*)&h11;
    g_packed[i] = r;
}

// ---------------------------------------------------------------------------
// Main: one thread per (sorted point, 4-level group). MLP=4 gathers.
// ---------------------------------------------------------------------------
__global__ __launch_bounds__(256) void hash_embed_kernel(
    float* __restrict__ out,
    int n_points,
    Params pm)
{
    __shared__ float s_resF[NLEV];
    __shared__ int   s_resI[NLEV];
    __shared__ int   s_off[NLEV];
    if (threadIdx.x < NLEV) {
        s_resF[threadIdx.x] = pm.resF[threadIdx.x];
        s_resI[threadIdx.x] = pm.resI[threadIdx.x];
        s_off[threadIdx.x]  = pm.off[threadIdx.x];
    }
    __syncthreads();

    int gid = blockIdx.x * blockDim.x + threadIdx.x;
    int p = gid >> 2;              // sorted point index (4 threads per point)
    if (p >= n_points) return;
    int lb = (gid & 3) << 2;       // base level: 0,4,8,12

    float2 xy = g_xy_sorted[p];    // 4 consecutive threads -> broadcast
    int orig  = g_orig[p];

    int   idx[4];
    float wx[4], wy[4];

#pragma unroll
    for (int j = 0; j < 4; ++j) {
        int   l   = lb + j;
        float res = s_resF[l];
        int   ri  = s_resI[l];
        int   off = s_off[l];

        float px = xy.x * res;
        float py = xy.y * res;
        float fx = floorf(px);
        float fy = floorf(py);
        wx[j] = px - fx;
        wy[j] = py - fy;

        int ix = min(max((int)fx, 0), ri - 1);
        int iy = min(max((int)fy, 0), ri - 1);
        idx[j] = off + iy * ri + ix;
    }

    uint4 r0 = __ldg(&g_packed[idx[0]]);
    uint4 r1 = __ldg(&g_packed[idx[1]]);
    uint4 r2 = __ldg(&g_packed[idx[2]]);
    uint4 r3 = __ldg(&g_packed[idx[3]]);

    float o[8];
    uint4 rr[4] = {r0, r1, r2, r3};
#pragma unroll
    for (int j = 0; j < 4; ++j) {
        float2 f00 = __half22float2(*(const half2*)&rr[j].x);
        float2 f10 = __half22float2(*(const half2*)&rr[j].y);
        float2 f01 = __half22float2(*(const half2*)&rr[j].z);
        float2 f11 = __half22float2(*(const half2*)&rr[j].w);

        float u = 1.0f - wx[j];
        float v = 1.0f - wy[j];

        o[2 * j]     = (f00.x * u + f10.x * wx[j]) * v + (f01.x * u + f11.x * wx[j]) * wy[j];
        o[2 * j + 1] = (f00.y * u + f10.y * wx[j]) * v + (f01.y * u + f11.y * wx[j]) * wy[j];
    }

    // Write 32B to the ORIGINAL point's output row.
    float4* dst = (float4*)(out + (size_t)orig * (NLEV * 2) + lb * 2);
    dst[0] = make_float4(o[0], o[1], o[2], o[3]);
    dst[1] = make_float4(o[4], o[5], o[6], o[7]);
}

extern "C" void kernel_launch(void* const* d_in, const int* in_sizes, int n_in,
                              void* d_out, int out_size)
{
    const float* x   = (const float*)d_in[0];
    const float* emb = (const float*)d_in[1];
    float* out       = (float*)d_out;

    int n_points = in_sizes[0] / 2;

    Params pm;
    double b = exp((log(512.0) - log(16.0)) / 15.0);
    int acc = 0;
    for (int l = 0; l < NLEV; ++l) {
        double r = floor(16.0 * pow(b, (double)l));
        pm.resF[l] = (float)r;
        pm.resI[l] = (int)r;
        pm.off[l]  = acc;
        acc += pm.resI[l] * pm.resI[l];
    }
    pm.off[NLEV] = acc;

    // Spatial counting sort
    zero_counts_kernel<<<(NBUCK + 255) / 256, 256>>>();
    hist_kernel<<<(n_points + 255) / 256, 256>>>(x, n_points);
    scan_kernel<<<1, 1024>>>();
    scatter_kernel<<<(n_points + 255) / 256, 256>>>(x, n_points);

    // Build packed corner table (independent of sort; can overlap on stream)
    {
        int threads = 256;
        int blocks = (acc + threads - 1) / threads;
        build_packed_kernel<<<blocks, threads>>>(emb, pm, acc);
    }

    // Main gather + lerp over sorted points
    {
        long long total = (long long)n_points * 4;
        int threads = 256;
        int blocks = (int)((total + threads - 1) / threads);
        hash_embed_kernel<<<blocks, threads>>>(out, n_points, pm);
    }
}

// round 9
// speedup vs baseline: 2.3547x; 2.3547x over previous
#include <cuda_runtime.h>
#include <cuda_fp16.h>
#include <math.h>
#include <stdint.h>

// HashEmbedder: 16-level 2D multires hash grid, 2 feats/level, T=2^19.
// Phase 1: build fp16 cell-packed corner table (16B per cell).
// Phase 2: 2 threads/point, 8 levels/thread. Fused idx+load loop keeps
// 8 LDG.128 in flight with <=51 regs -> 40 warps/SM -> ~320 in-flight
// gathers/SM (saturates the ~1 wf/cyc l1tex pipe).

#define NLEV 16
#define TLOG2 19
#define TSIZE (1u << TLOG2)
#define HMASK ((1u << TLOG2) - 1u)
#define PRIME1 2654435761u

// Sum of res^2 over the 16 levels = 706,816 cells; margin for safety.
#define MAX_CELLS 710000
__device__ uint4 g_packed[MAX_CELLS];   // 16B per cell: h00,h10,h01,h11

struct Params {
    float resF[NLEV];
    int   resI[NLEV];
    int   off[NLEV + 1];
};

// ---------------------------------------------------------------------------
// Phase 1: build packed table. One thread per cell.
// ---------------------------------------------------------------------------
__global__ __launch_bounds__(256) void build_packed_kernel(
    const float* __restrict__ emb, Params pm, int total_cells)
{
    int i = blockIdx.x * blockDim.x + threadIdx.x;
    if (i >= total_cells) return;

    int l = 0;
#pragma unroll
    for (int k = 1; k < NLEV; ++k) l += (i >= pm.off[k]);

    int c   = i - pm.off[l];
    int res = pm.resI[l];
    int cy  = c / res;
    int cx  = c - cy * res;

    uint32_t ux0 = (uint32_t)cx;
    uint32_t ux1 = (uint32_t)(cx + 1);
    uint32_t yp0 = (uint32_t)cy * PRIME1;
    uint32_t yp1 = (uint32_t)(cy + 1) * PRIME1;

    uint32_t a00 = (ux0 ^ yp0) & HMASK;
    uint32_t a10 = (ux1 ^ yp0) & HMASK;
    uint32_t a01 = (ux0 ^ yp1) & HMASK;
    uint32_t a11 = (ux1 ^ yp1) & HMASK;

    const float2* __restrict__ tab =
        ((const float2*)emb) + ((size_t)l << TLOG2);

    float2 f00 = __ldg(tab + a00);
    float2 f10 = __ldg(tab + a10);
    float2 f01 = __ldg(tab + a01);
    float2 f11 = __ldg(tab + a11);

    half2 h00 = __float22half2_rn(f00);
    half2 h10 = __float22half2_rn(f10);
    half2 h01 = __float22half2_rn(f01);
    half2 h11 = __float22half2_rn(f11);

    uint4 r;
    r.x = *(const uint32_t*)&h00;
    r.y = *(const uint32_t*)&h10;
    r.z = *(const uint32_t*)&h01;
    r.w = *(const uint32_t*)&h11;
    g_packed[i] = r;
}

// ---------------------------------------------------------------------------
// Phase 2: one thread per (point, 8-level group), register-disciplined.
// ---------------------------------------------------------------------------
__global__ __launch_bounds__(128, 10) void hash_embed_kernel(
    const float* __restrict__ x,
    float* __restrict__ out,
    int n_points,
    Params pm)
{
    __shared__ float s_resF[NLEV];
    __shared__ int   s_resI[NLEV];
    __shared__ int   s_off[NLEV];
    if (threadIdx.x < NLEV) {
        s_resF[threadIdx.x] = pm.resF[threadIdx.x];
        s_resI[threadIdx.x] = pm.resI[threadIdx.x];
        s_off[threadIdx.x]  = pm.off[threadIdx.x];
    }
    __syncthreads();

    int gid = blockIdx.x * blockDim.x + threadIdx.x;
    int p = gid >> 1;              // point index (2 threads per point)
    if (p >= n_points) return;
    int lb = (gid & 1) << 3;       // base level: 0 or 8

    // 2 consecutive threads read the same point -> broadcast load
    float2 xy = __ldg(((const float2*)x) + p);

    // Fused index-compute + load: idx is transient (1 live reg), the 8
    // uint4 results accumulate in flight.
    uint4 rr[8];
#pragma unroll
    for (int j = 0; j < 8; ++j) {
        int   l   = lb + j;
        float res = s_resF[l];
        int   ri  = s_resI[l];
        int   off = s_off[l];

        int ix = min(max((int)floorf(xy.x * res), 0), ri - 1);
        int iy = min(max((int)floorf(xy.y * res), 0), ri - 1);
        rr[j] = __ldg(&g_packed[off + iy * ri + ix]);
    }

    // Lerp loop: consumes rr[j] in issue order; wx/wy rematerialized.
    float4 o[4];
#pragma unroll
    for (int j = 0; j < 8; ++j) {
        float res = s_resF[lb + j];
        float px = xy.x * res;
        float py = xy.y * res;
        float wx = px - floorf(px);
        float wy = py - floorf(py);

        float2 f00 = __half22float2(*(const half2*)&rr[j].x);
        float2 f10 = __half22float2(*(const half2*)&rr[j].y);
        float2 f01 = __half22float2(*(const half2*)&rr[j].z);
        float2 f11 = __half22float2(*(const half2*)&rr[j].w);

        float u = 1.0f - wx;
        float v = 1.0f - wy;

        ((float*)o)[2 * j]     = (f00.x * u + f10.x * wx) * v + (f01.x * u + f11.x * wx) * wy;
        ((float*)o)[2 * j + 1] = (f00.y * u + f10.y * wx) * v + (f01.y * u + f11.y * wx) * wy;
    }

    // out row = p*32 floats; this thread covers floats [lb*2, lb*2+16) = 64B.
    // 2 threads per point -> a full 128B line, perfectly coalesced.
    float4* dst = (float4*)(out + (size_t)p * (NLEV * 2) + lb * 2);
    dst[0] = o[0];
    dst[1] = o[1];
    dst[2] = o[2];
    dst[3] = o[3];
}

extern "C" void kernel_launch(void* const* d_in, const int* in_sizes, int n_in,
                              void* d_out, int out_size)
{
    const float* x   = (const float*)d_in[0];
    const float* emb = (const float*)d_in[1];
    float* out       = (float*)d_out;

    int n_points = in_sizes[0] / 2;

    Params pm;
    double b = exp((log(512.0) - log(16.0)) / 15.0);
    int acc = 0;
    for (int l = 0; l < NLEV; ++l) {
        double r = floor(16.0 * pow(b, (double)l));
        pm.resF[l] = (float)r;
        pm.resI[l] = (int)r;
        pm.off[l]  = acc;
        acc += pm.resI[l] * pm.resI[l];
    }
    pm.off[NLEV] = acc;

    // Phase 1: build packed corner table (fp16, 16B per cell)
    {
        int threads = 256;
        int blocks = (acc + threads - 1) / threads;
        build_packed_kernel<<<blocks, threads>>>(emb, pm, acc);
    }

    // Phase 2: gather + lerp, 2 threads per point
    {
        long long total = (long long)n_points * 2;
        int threads = 128;
        int blocks = (int)((total + threads - 1) / threads);
        hash_embed_kernel<<<blocks, threads>>>(x, out, n_points, pm);
    }
}